// round 12
// baseline (speedup 1.0000x reference)
#include <cuda_runtime.h>
#include <cuda_fp16.h>
#include <cstdint>

// Problem constants
#define Bq 2
#define Sq 2048
#define DIMq 2048
#define NHq 32
#define NKVq 8
#define HDq 64
#define NTOK (Bq * Sq)          // 4096
#define QDIM (NHq * HDq)        // 2048
#define KVDIM (NKVq * HDq)      // 512
#define NCAT (QDIM + 2 * KVDIM) // 3072

// ---------------------------------------------------------------------------
// Scratch (__device__ globals; no allocation allowed)
// ---------------------------------------------------------------------------
__device__ __align__(16) __half g_Xh[NTOK * DIMq];     // 16 MB fp16 x
__device__ __align__(16) __half g_Wcat[DIMq * NCAT];   // 12 MB [K, Nq|Nk|Nv]
__device__ __align__(16) __half g_Woh[QDIM * DIMq];    // 8 MB
__device__ __align__(16) __half g_Q[NTOK * QDIM];      // 16 MB (post-RoPE)
__device__ __align__(16) __half g_K[NTOK * KVDIM];     // 4 MB
__device__ __align__(16) __half g_V[NTOK * KVDIM];     // 4 MB
__device__ __align__(16) __half g_O[NTOK * QDIM];      // 16 MB

__device__ __forceinline__ uint32_t s2u(const void* p) {
    return (uint32_t)__cvta_generic_to_shared(p);
}
__device__ __forceinline__ uint32_t f2h2u(float x, float y) {
    __half2 h = __floats2half2_rn(x, y);
    return *(uint32_t*)&h;
}

#define LDSM4(r0, r1, r2, r3, addr)                                          \
    asm volatile("ldmatrix.sync.aligned.m8n8.x4.shared.b16 {%0,%1,%2,%3}, [%4];" \
                 : "=r"(r0), "=r"(r1), "=r"(r2), "=r"(r3) : "r"(addr))
#define LDSM4T(r0, r1, r2, r3, addr)                                         \
    asm volatile("ldmatrix.sync.aligned.m8n8.x4.trans.shared.b16 {%0,%1,%2,%3}, [%4];" \
                 : "=r"(r0), "=r"(r1), "=r"(r2), "=r"(r3) : "r"(addr))
#define MMA_F16(c, a0, a1, a2, a3, b0, b1)                                   \
    asm volatile(                                                            \
        "mma.sync.aligned.m16n8k16.row.col.f32.f16.f16.f32 "                 \
        "{%0,%1,%2,%3}, {%4,%5,%6,%7}, {%8,%9}, {%0,%1,%2,%3};"              \
        : "+f"((c)[0]), "+f"((c)[1]), "+f"((c)[2]), "+f"((c)[3])             \
        : "r"(a0), "r"(a1), "r"(a2), "r"(a3), "r"(b0), "r"(b1))
#define CP16(dst, src)                                                       \
    asm volatile("cp.async.ca.shared.global [%0], [%1], 16;"                 \
                 :: "r"(dst), "l"(src) : "memory")
#define CP_COMMIT() asm volatile("cp.async.commit_group;" ::: "memory")
#define CP_WAIT1()  asm volatile("cp.async.wait_group 1;" ::: "memory")

// ---------------------------------------------------------------------------
// One fused fp32->fp16 staging kernel (2048 elems/block).
// ---------------------------------------------------------------------------
__global__ void stage_all(
    const float* __restrict__ x, const float* __restrict__ Wq,
    const float* __restrict__ Wk, const float* __restrict__ Wv,
    const float* __restrict__ Wo,
    __half* __restrict__ Xh, __half* __restrict__ Wcat, __half* __restrict__ Woh)
{
    const int blk = blockIdx.x;
    const int t8  = threadIdx.x * 8;
    const float* src;
    __half* dst;
    if (blk < 4096) {
        int i = blk * 2048 + t8;
        src = x + i;
        dst = Xh + i;
    } else if (blk < 6144) {
        int i = (blk - 4096) * 2048 + t8;
        src = Wq + i;
        dst = Wcat + (size_t)(i / QDIM) * NCAT + (i % QDIM);
    } else if (blk < 6656) {
        int i = (blk - 6144) * 2048 + t8;
        src = Wk + i;
        dst = Wcat + (size_t)(i / KVDIM) * NCAT + QDIM + (i % KVDIM);
    } else if (blk < 7168) {
        int i = (blk - 6656) * 2048 + t8;
        src = Wv + i;
        dst = Wcat + (size_t)(i / KVDIM) * NCAT + QDIM + KVDIM + (i % KVDIM);
    } else {
        int i = (blk - 7168) * 2048 + t8;
        src = Wo + i;
        dst = Woh + i;
    }
    float4 a = *(const float4*)src;
    float4 b = *(const float4*)(src + 4);
    uint4 u;
    u.x = f2h2u(a.x, a.y);
    u.y = f2h2u(a.z, a.w);
    u.z = f2h2u(b.x, b.y);
    u.w = f2h2u(b.z, b.w);
    *(uint4*)dst = u;
}

// ---------------------------------------------------------------------------
// GEMM mainloop: CTA tile 128x128, 128 threads, 4 warps (2x2) of 64x64 tiles.
// BK=32, 3-stage cp.async ring, one __syncthreads per chunk, 2 CTAs/SM.
// Dynamic smem: As[3][128][40] + Bs[3][32][136] halfs = 56832 B per CTA.
// ---------------------------------------------------------------------------
#define AS_STAGE (128 * 40)
#define BS_STAGE (32 * 136)
#define GEMM_SMEM ((3 * AS_STAGE + 3 * BS_STAGE) * 2)  // 56832 B

struct GemmCtx {
    int wm, wn, g, tg;
    float acc[4][8][4];
};

__device__ __forceinline__ void gemm_mainloop(
    const __half* __restrict__ A, const __half* __restrict__ B,
    int N, int K, int brow, int bcol, __half* gsm, GemmCtx& cx)
{
    __half (*As)[128][40] = (__half(*)[128][40])gsm;
    __half (*Bs)[32][136] = (__half(*)[32][136])(gsm + 3 * AS_STAGE);

    const int tid = threadIdx.x;
    const int wid = tid >> 5;
    const int lid = tid & 31;
    cx.g  = lid >> 2;
    cx.tg = lid & 3;
    cx.wm = (wid & 1) * 64;
    cx.wn = (wid >> 1) * 64;

    // Loaders (128 thr): A 128x32 -> 1 row/thr, 4 CP16; B 32x128 -> 4 thr/row, 4 CP16.
    const int ar = tid;
    const int brr = tid >> 2, bcc = (tid & 3) * 32;
    const __half* Ap = A + (size_t)(brow + ar) * K;
    const __half* Bp = B + (size_t)brr * N + bcol + bcc;

    const int a_r = cx.wm + (lid & 15);
    const int a_c = 8 * (lid >> 4);
    const int b_k = (lid & 7) + 8 * ((lid >> 3) & 1);
    const int b_n = 8 * (lid >> 4);

#pragma unroll
    for (int mi = 0; mi < 4; mi++)
#pragma unroll
        for (int ni = 0; ni < 8; ni++)
#pragma unroll
            for (int q = 0; q < 4; q++) cx.acc[mi][ni][q] = 0.f;

    const int NC = K >> 5;

    // Prologue: chunks 0,1 -> stages 0,1
#pragma unroll
    for (int s = 0; s < 2; s++) {
        const __half* An = Ap + (s << 5);
        const __half* Bn = Bp + (size_t)(s << 5) * N;
#pragma unroll
        for (int j = 0; j < 4; j++) {
            CP16(s2u(&As[s][ar][8 * j]), An + 8 * j);
            CP16(s2u(&Bs[s][brr][bcc + 8 * j]), Bn + 8 * j);
        }
        CP_COMMIT();
    }

    for (int kc = 0; kc < NC; kc++) {
        CP_WAIT1();
        __syncthreads();

        const int cur = kc % 3;
#pragma unroll
        for (int ks = 0; ks < 2; ks++) {
            uint32_t af[4][4];
#pragma unroll
            for (int mi = 0; mi < 4; mi++)
                LDSM4(af[mi][0], af[mi][1], af[mi][2], af[mi][3],
                      s2u(&As[cur][a_r + mi * 16][ks * 16 + a_c]));
            uint32_t bf[8][2];
#pragma unroll
            for (int nq = 0; nq < 4; nq++)
                LDSM4T(bf[2 * nq][0], bf[2 * nq][1],
                       bf[2 * nq + 1][0], bf[2 * nq + 1][1],
                       s2u(&Bs[cur][ks * 16 + b_k][cx.wn + nq * 16 + b_n]));
#pragma unroll
            for (int mi = 0; mi < 4; mi++)
#pragma unroll
                for (int ni = 0; ni < 8; ni++)
                    MMA_F16(cx.acc[mi][ni], af[mi][0], af[mi][1], af[mi][2], af[mi][3],
                            bf[ni][0], bf[ni][1]);
        }

        const int nxt = kc + 2;
        if (nxt < NC) {
            const int sb = nxt % 3;
            const __half* An = Ap + (nxt << 5);
            const __half* Bn = Bp + (size_t)(nxt << 5) * N;
#pragma unroll
            for (int j = 0; j < 4; j++) {
                CP16(s2u(&As[sb][ar][8 * j]), An + 8 * j);
                CP16(s2u(&Bs[sb][brr][bcc + 8 * j]), Bn + 8 * j);
            }
        }
        CP_COMMIT();
    }
}

// ---------------------------------------------------------------------------
// Fused QKV projection: X @ Wcat -> Q (RoPE), K (RoPE), V, all fp16.
// CTA 128x128; region is CTA-uniform.
// ---------------------------------------------------------------------------
__global__ __launch_bounds__(128, 2) void gemm_qkv(
    const __half* __restrict__ X, const __half* __restrict__ Wc,
    __half* __restrict__ Q, __half* __restrict__ K, __half* __restrict__ V,
    const float* __restrict__ cs, const float* __restrict__ sn)
{
    extern __shared__ __half gsm[];
    const int brow = blockIdx.y * 128;
    const int bcol = blockIdx.x * 128;

    GemmCtx cx;
    gemm_mainloop(X, Wc, NCAT, DIMq, brow, bcol, gsm, cx);

    __half* C;
    int coff, Nout;
    bool rope;
    if (bcol < QDIM)              { C = Q; coff = 0;            Nout = QDIM;  rope = true;  }
    else if (bcol < QDIM + KVDIM) { C = K; coff = QDIM;         Nout = KVDIM; rope = true;  }
    else                          { C = V; coff = QDIM + KVDIM; Nout = KVDIM; rope = false; }

#pragma unroll
    for (int mi = 0; mi < 4; mi++) {
#pragma unroll
        for (int ni = 0; ni < 8; ni++) {
            const int row = brow + cx.wm + mi * 16 + cx.g;
            const int col = bcol - coff + cx.wn + ni * 8 + 2 * cx.tg;
            float* a = cx.acc[mi][ni];
            if (rope) {
                const int pair = (col & 63) >> 1;
                const int sp0 = row & (Sq - 1);
                const int sp1 = (row + 8) & (Sq - 1);
                float c0 = cs[sp0 * 32 + pair], s0 = sn[sp0 * 32 + pair];
                float c1 = cs[sp1 * 32 + pair], s1 = sn[sp1 * 32 + pair];
                *(__half2*)&C[(size_t)row * Nout + col] =
                    __floats2half2_rn(a[0] * c0 - a[1] * s0, a[0] * s0 + a[1] * c0);
                *(__half2*)&C[(size_t)(row + 8) * Nout + col] =
                    __floats2half2_rn(a[2] * c1 - a[3] * s1, a[2] * s1 + a[3] * c1);
            } else {
                *(__half2*)&C[(size_t)row * Nout + col] = __floats2half2_rn(a[0], a[1]);
                *(__half2*)&C[(size_t)(row + 8) * Nout + col] = __floats2half2_rn(a[2], a[3]);
            }
        }
    }
}

// ---------------------------------------------------------------------------
// Output projection: O @ Wo -> out (fp32). CTA 128x128.
// ---------------------------------------------------------------------------
__global__ __launch_bounds__(128, 2) void gemm_out(
    const __half* __restrict__ A, const __half* __restrict__ B,
    float* __restrict__ C, int N, int K)
{
    extern __shared__ __half gsm[];
    const int brow = blockIdx.y * 128;
    const int bcol = blockIdx.x * 128;

    GemmCtx cx;
    gemm_mainloop(A, B, N, K, brow, bcol, gsm, cx);

#pragma unroll
    for (int mi = 0; mi < 4; mi++) {
#pragma unroll
        for (int ni = 0; ni < 8; ni++) {
            const int row = brow + cx.wm + mi * 16 + cx.g;
            const int col = bcol + cx.wn + ni * 8 + 2 * cx.tg;
            *(float2*)&C[(size_t)row * N + col] =
                make_float2(cx.acc[mi][ni][0], cx.acc[mi][ni][1]);
            *(float2*)&C[(size_t)(row + 8) * N + col] =
                make_float2(cx.acc[mi][ni][2], cx.acc[mi][ni][3]);
        }
    }
}

// ---------------------------------------------------------------------------
// fp16 flash attention (causal, GQA 4:1) — unchanged from R10/R11.
// ---------------------------------------------------------------------------
#define FS 72
#define KV_STAGE (128 * FS)
#define FLASH_SMEM (3 * KV_STAGE * 2)  // 55296 B

__global__ __launch_bounds__(256, 2) void flash_h(
    const __half* __restrict__ Q, const __half* __restrict__ K,
    const __half* __restrict__ V, __half* __restrict__ O)
{
    extern __shared__ __half fsm[];

    const int bh  = blockIdx.y;
    const int b   = bh >> 5;
    const int h   = bh & 31;
    const int kvh = h >> 2;
    const int qb  = gridDim.x - 1 - blockIdx.x;
    const int q0  = qb * 128;

    const int tid = threadIdx.x;
    const int wid = tid >> 5;
    const int lid = tid & 31;
    const int g   = lid >> 2;
    const int tg  = lid & 3;
    const int wq  = wid * 16;

    const int a_r = (lid & 15);
    const int a_c = 8 * (lid >> 4);
    const int nt_r = (lid & 7) + 8 * (lid >> 4);
    const int nt_c = 8 * ((lid >> 3) & 1);
    const int tr_r = (lid & 7) + 8 * ((lid >> 3) & 1);
    const int tr_c = 8 * (lid >> 4);

    {
        __half* Qs = fsm;
        const int row = tid >> 1, c0 = (tid & 1) * 32;
        const __half* src = &Q[((size_t)(b * Sq + q0 + row)) * QDIM + h * HDq + c0];
        const __half2 hs = __floats2half2_rn(0.125f, 0.125f);
#pragma unroll
        for (int i = 0; i < 4; i++) {
            uint4 u = *(const uint4*)(src + 8 * i);
            __half2* hp = (__half2*)&u;
#pragma unroll
            for (int j = 0; j < 4; j++) hp[j] = __hmul2(hp[j], hs);
            *(uint4*)&Qs[row * FS + c0 + 8 * i] = u;
        }
    }
    __syncthreads();

    uint32_t qf[4][4];
#pragma unroll
    for (int kc = 0; kc < 4; kc++)
        LDSM4(qf[kc][0], qf[kc][1], qf[kc][2], qf[kc][3],
              s2u(&fsm[(wq + a_r) * FS + kc * 16 + a_c]));
    __syncthreads();

    float oacc[8][4];
#pragma unroll
    for (int nj = 0; nj < 8; nj++)
#pragma unroll
        for (int q = 0; q < 4; q++) oacc[nj][q] = 0.f;
    float m0 = -1e30f, m1 = -1e30f, l0 = 0.f, l1 = 0.f;

    const int ntiles = 2 * qb + 2;
    const int row0 = q0 + wq + g;
    const int row1 = row0 + 8;

    const int kvrow = tid >> 2, kvc = (tid & 3) * 16;
    const size_t kvbase = ((size_t)b * Sq + kvrow) * KVDIM + kvh * HDq + kvc;

#pragma unroll
    for (int s = 0; s < 2; s++) {
        __half* Ks = fsm + s * KV_STAGE;
        __half* Vs = Ks + 64 * FS;
        const size_t off = kvbase + (size_t)s * 64 * KVDIM;
#pragma unroll
        for (int i = 0; i < 2; i++) {
            CP16(s2u(&Ks[kvrow * FS + kvc + 8 * i]), K + off + 8 * i);
            CP16(s2u(&Vs[kvrow * FS + kvc + 8 * i]), V + off + 8 * i);
        }
        CP_COMMIT();
    }

    for (int t = 0; t < ntiles; t++) {
        CP_WAIT1();
        __syncthreads();

        const __half* Ks = fsm + (t % 3) * KV_STAGE;
        const __half* Vs = Ks + 64 * FS;
        const int tb = t * 64;

        float sacc[8][4];
#pragma unroll
        for (int ni = 0; ni < 8; ni++)
#pragma unroll
            for (int q = 0; q < 4; q++) sacc[ni][q] = 0.f;

#pragma unroll
        for (int kc = 0; kc < 4; kc++) {
#pragma unroll
            for (int ng = 0; ng < 4; ng++) {
                uint32_t kf[4];
                LDSM4(kf[0], kf[1], kf[2], kf[3],
                      s2u(&Ks[(ng * 16 + nt_r) * FS + kc * 16 + nt_c]));
                MMA_F16(sacc[2 * ng],     qf[kc][0], qf[kc][1], qf[kc][2], qf[kc][3], kf[0], kf[1]);
                MMA_F16(sacc[2 * ng + 1], qf[kc][0], qf[kc][1], qf[kc][2], qf[kc][3], kf[2], kf[3]);
            }
        }

        if (tb + 63 > q0 + wq) {
#pragma unroll
            for (int ni = 0; ni < 8; ni++) {
                int key = tb + 8 * ni + 2 * tg;
                if (key > row0)     sacc[ni][0] = -1e30f;
                if (key + 1 > row0) sacc[ni][1] = -1e30f;
                if (key > row1)     sacc[ni][2] = -1e30f;
                if (key + 1 > row1) sacc[ni][3] = -1e30f;
            }
        }

        float tmax0 = -1e30f, tmax1 = -1e30f;
#pragma unroll
        for (int ni = 0; ni < 8; ni++) {
            tmax0 = fmaxf(tmax0, fmaxf(sacc[ni][0], sacc[ni][1]));
            tmax1 = fmaxf(tmax1, fmaxf(sacc[ni][2], sacc[ni][3]));
        }
        tmax0 = fmaxf(tmax0, __shfl_xor_sync(0xffffffff, tmax0, 1));
        tmax0 = fmaxf(tmax0, __shfl_xor_sync(0xffffffff, tmax0, 2));
        tmax1 = fmaxf(tmax1, __shfl_xor_sync(0xffffffff, tmax1, 1));
        tmax1 = fmaxf(tmax1, __shfl_xor_sync(0xffffffff, tmax1, 2));

        float nm0 = fmaxf(m0, tmax0);
        float nm1 = fmaxf(m1, tmax1);
        float corr0 = __expf(m0 - nm0);
        float corr1 = __expf(m1 - nm1);

        float rs0 = 0.f, rs1 = 0.f;
#pragma unroll
        for (int ni = 0; ni < 8; ni++) {
            sacc[ni][0] = __expf(sacc[ni][0] - nm0);
            sacc[ni][1] = __expf(sacc[ni][1] - nm0);
            sacc[ni][2] = __expf(sacc[ni][2] - nm1);
            sacc[ni][3] = __expf(sacc[ni][3] - nm1);
            rs0 += sacc[ni][0] + sacc[ni][1];
            rs1 += sacc[ni][2] + sacc[ni][3];
        }
        rs0 += __shfl_xor_sync(0xffffffff, rs0, 1);
        rs0 += __shfl_xor_sync(0xffffffff, rs0, 2);
        rs1 += __shfl_xor_sync(0xffffffff, rs1, 1);
        rs1 += __shfl_xor_sync(0xffffffff, rs1, 2);

        l0 = l0 * corr0 + rs0;
        l1 = l1 * corr1 + rs1;
#pragma unroll
        for (int nj = 0; nj < 8; nj++) {
            oacc[nj][0] *= corr0;
            oacc[nj][1] *= corr0;
            oacc[nj][2] *= corr1;
            oacc[nj][3] *= corr1;
        }
        m0 = nm0;
        m1 = nm1;

#pragma unroll
        for (int kc = 0; kc < 4; kc++) {
            uint32_t a0 = f2h2u(sacc[2 * kc][0], sacc[2 * kc][1]);
            uint32_t a1 = f2h2u(sacc[2 * kc][2], sacc[2 * kc][3]);
            uint32_t a2 = f2h2u(sacc[2 * kc + 1][0], sacc[2 * kc + 1][1]);
            uint32_t a3 = f2h2u(sacc[2 * kc + 1][2], sacc[2 * kc + 1][3]);
#pragma unroll
            for (int ng = 0; ng < 4; ng++) {
                uint32_t vf[4];
                LDSM4T(vf[0], vf[1], vf[2], vf[3],
                       s2u(&Vs[(kc * 16 + tr_r) * FS + ng * 16 + tr_c]));
                MMA_F16(oacc[2 * ng],     a0, a1, a2, a3, vf[0], vf[1]);
                MMA_F16(oacc[2 * ng + 1], a0, a1, a2, a3, vf[2], vf[3]);
            }
        }

        const int nxt = t + 2;
        if (nxt < ntiles) {
            __half* Kn = fsm + (nxt % 3) * KV_STAGE;
            __half* Vn = Kn + 64 * FS;
            const size_t off = kvbase + (size_t)nxt * 64 * KVDIM;
#pragma unroll
            for (int i = 0; i < 2; i++) {
                CP16(s2u(&Kn[kvrow * FS + kvc + 8 * i]), K + off + 8 * i);
                CP16(s2u(&Vn[kvrow * FS + kvc + 8 * i]), V + off + 8 * i);
            }
        }
        CP_COMMIT();
    }

    float inv0 = 1.f / l0;
    float inv1 = 1.f / l1;
    const size_t tok0 = (size_t)b * Sq + row0;
#pragma unroll
    for (int nj = 0; nj < 8; nj++) {
        const int col = h * HDq + 8 * nj + 2 * tg;
        *(__half2*)&O[tok0 * QDIM + col] =
            __floats2half2_rn(oacc[nj][0] * inv0, oacc[nj][1] * inv0);
        *(__half2*)&O[(tok0 + 8) * QDIM + col] =
            __floats2half2_rn(oacc[nj][2] * inv1, oacc[nj][3] * inv1);
    }
}

// ---------------------------------------------------------------------------
// Launch
// ---------------------------------------------------------------------------
extern "C" void kernel_launch(void* const* d_in, const int* in_sizes, int n_in,
                              void* d_out, int out_size)
{
    const float* x   = (const float*)d_in[0];
    const float* cs  = (const float*)d_in[1];
    const float* sn  = (const float*)d_in[2];
    const float* Wq  = (const float*)d_in[3];
    const float* Wk  = (const float*)d_in[4];
    const float* Wv  = (const float*)d_in[5];
    const float* Wo  = (const float*)d_in[6];
    float* out = (float*)d_out;

    __half *Xh, *Wcat, *Woh, *Q, *K, *V, *O;
    cudaGetSymbolAddress((void**)&Xh, g_Xh);
    cudaGetSymbolAddress((void**)&Wcat, g_Wcat);
    cudaGetSymbolAddress((void**)&Woh, g_Woh);
    cudaGetSymbolAddress((void**)&Q, g_Q);
    cudaGetSymbolAddress((void**)&K, g_K);
    cudaGetSymbolAddress((void**)&V, g_V);
    cudaGetSymbolAddress((void**)&O, g_O);

    cudaFuncSetAttribute(gemm_qkv, cudaFuncAttributeMaxDynamicSharedMemorySize, GEMM_SMEM);
    cudaFuncSetAttribute(gemm_out, cudaFuncAttributeMaxDynamicSharedMemorySize, GEMM_SMEM);
    cudaFuncSetAttribute(flash_h, cudaFuncAttributeMaxDynamicSharedMemorySize, FLASH_SMEM);

    // One fused staging kernel
    stage_all<<<9216, 256>>>(x, Wq, Wk, Wv, Wo, Xh, Wcat, Woh);

    // Fused QKV projection (+RoPE on Q,K): CTA 128x128, 128 threads, 2 CTA/SM
    gemm_qkv<<<dim3(NCAT / 128, NTOK / 128), 128, GEMM_SMEM>>>(Xh, Wcat, Q, K, V, cs, sn);

    // fp16 flash attention
    flash_h<<<dim3(Sq / 128, Bq * NHq), 256, FLASH_SMEM>>>(Q, K, V, O);

    // Output projection (fp32 out): CTA 128x128, 128 threads, 2 CTA/SM
    gemm_out<<<dim3(DIMq / 128, NTOK / 128), 128, GEMM_SMEM>>>(O, Woh, out, DIMq, QDIM);
}

// round 13
// speedup vs baseline: 1.1522x; 1.1522x over previous
#include <cuda_runtime.h>
#include <cuda_fp16.h>
#include <cstdint>

// Problem constants
#define Bq 2
#define Sq 2048
#define DIMq 2048
#define NHq 32
#define NKVq 8
#define HDq 64
#define NTOK (Bq * Sq)          // 4096
#define QDIM (NHq * HDq)        // 2048
#define KVDIM (NKVq * HDq)      // 512
#define NCAT (QDIM + 2 * KVDIM) // 3072

// ---------------------------------------------------------------------------
// Scratch (__device__ globals; no allocation allowed)
// ---------------------------------------------------------------------------
__device__ __align__(16) __half g_Xh[NTOK * DIMq];     // 16 MB fp16 x
__device__ __align__(16) __half g_Wcat[DIMq * NCAT];   // 12 MB [K, Nq|Nk|Nv]
__device__ __align__(16) __half g_Woh[QDIM * DIMq];    // 8 MB
__device__ __align__(16) __half g_Q[NTOK * QDIM];      // 16 MB (post-RoPE)
__device__ __align__(16) __half g_K[NTOK * KVDIM];     // 4 MB
__device__ __align__(16) __half g_V[NTOK * KVDIM];     // 4 MB
__device__ __align__(16) __half g_O[NTOK * QDIM];      // 16 MB

__device__ __forceinline__ uint32_t s2u(const void* p) {
    return (uint32_t)__cvta_generic_to_shared(p);
}
__device__ __forceinline__ uint32_t f2h2u(float x, float y) {
    __half2 h = __floats2half2_rn(x, y);
    return *(uint32_t*)&h;
}

#define LDSM4(r0, r1, r2, r3, addr)                                          \
    asm volatile("ldmatrix.sync.aligned.m8n8.x4.shared.b16 {%0,%1,%2,%3}, [%4];" \
                 : "=r"(r0), "=r"(r1), "=r"(r2), "=r"(r3) : "r"(addr))
#define LDSM4T(r0, r1, r2, r3, addr)                                         \
    asm volatile("ldmatrix.sync.aligned.m8n8.x4.trans.shared.b16 {%0,%1,%2,%3}, [%4];" \
                 : "=r"(r0), "=r"(r1), "=r"(r2), "=r"(r3) : "r"(addr))
#define MMA_F16(c, a0, a1, a2, a3, b0, b1)                                   \
    asm volatile(                                                            \
        "mma.sync.aligned.m16n8k16.row.col.f32.f16.f16.f32 "                 \
        "{%0,%1,%2,%3}, {%4,%5,%6,%7}, {%8,%9}, {%0,%1,%2,%3};"              \
        : "+f"((c)[0]), "+f"((c)[1]), "+f"((c)[2]), "+f"((c)[3])             \
        : "r"(a0), "r"(a1), "r"(a2), "r"(a3), "r"(b0), "r"(b1))
#define CP16(dst, src)                                                       \
    asm volatile("cp.async.ca.shared.global [%0], [%1], 16;"                 \
                 :: "r"(dst), "l"(src) : "memory")
#define CP_COMMIT() asm volatile("cp.async.commit_group;" ::: "memory")
#define CP_WAIT1()  asm volatile("cp.async.wait_group 1;" ::: "memory")

// ---------------------------------------------------------------------------
// One fused fp32->fp16 staging kernel (2048 elems/block).
// ---------------------------------------------------------------------------
__global__ void stage_all(
    const float* __restrict__ x, const float* __restrict__ Wq,
    const float* __restrict__ Wk, const float* __restrict__ Wv,
    const float* __restrict__ Wo,
    __half* __restrict__ Xh, __half* __restrict__ Wcat, __half* __restrict__ Woh)
{
    const int blk = blockIdx.x;
    const int t8  = threadIdx.x * 8;
    const float* src;
    __half* dst;
    if (blk < 4096) {
        int i = blk * 2048 + t8;
        src = x + i;
        dst = Xh + i;
    } else if (blk < 6144) {
        int i = (blk - 4096) * 2048 + t8;
        src = Wq + i;
        dst = Wcat + (size_t)(i / QDIM) * NCAT + (i % QDIM);
    } else if (blk < 6656) {
        int i = (blk - 6144) * 2048 + t8;
        src = Wk + i;
        dst = Wcat + (size_t)(i / KVDIM) * NCAT + QDIM + (i % KVDIM);
    } else if (blk < 7168) {
        int i = (blk - 6656) * 2048 + t8;
        src = Wv + i;
        dst = Wcat + (size_t)(i / KVDIM) * NCAT + QDIM + KVDIM + (i % KVDIM);
    } else {
        int i = (blk - 7168) * 2048 + t8;
        src = Wo + i;
        dst = Woh + i;
    }
    float4 a = *(const float4*)src;
    float4 b = *(const float4*)(src + 4);
    uint4 u;
    u.x = f2h2u(a.x, a.y);
    u.y = f2h2u(a.z, a.w);
    u.z = f2h2u(b.x, b.y);
    u.w = f2h2u(b.z, b.w);
    *(uint4*)dst = u;
}

// ===========================================================================
// Variant A (R10): CTA 128x128, 256 thr, 8 warps (2x4) of 64x32, 2 CTA/SM.
// Dynamic smem: As[3][128][40] + Bs[3][32][136] = 56832 B.
// ===========================================================================
#define AS_STAGE_A (128 * 40)
#define BS_STAGE_A (32 * 136)
#define GEMM_SMEM_A ((3 * AS_STAGE_A + 3 * BS_STAGE_A) * 2)  // 56832 B

struct CtxA {
    int wm, wn, g, tg;
    float acc[4][4][4];
};

__device__ __forceinline__ void mainloop_a(
    const __half* __restrict__ A, const __half* __restrict__ B,
    int N, int K, int brow, int bcol, __half* gsm, CtxA& cx)
{
    __half (*As)[128][40] = (__half(*)[128][40])gsm;
    __half (*Bs)[32][136] = (__half(*)[32][136])(gsm + 3 * AS_STAGE_A);

    const int tid = threadIdx.x;
    const int wid = tid >> 5;
    const int lid = tid & 31;
    cx.g  = lid >> 2;
    cx.tg = lid & 3;
    cx.wm = (wid & 1) * 64;
    cx.wn = (wid >> 1) * 32;

    const int ar = tid >> 1, ac = (tid & 1) * 16;
    const int brr = tid >> 3, bcc = (tid & 7) * 16;
    const __half* Ap = A + (size_t)(brow + ar) * K + ac;
    const __half* Bp = B + (size_t)brr * N + bcol + bcc;

    const int a_r = cx.wm + (lid & 15);
    const int a_c = 8 * (lid >> 4);
    const int b_k = (lid & 7) + 8 * ((lid >> 3) & 1);
    const int b_n = 8 * (lid >> 4);

#pragma unroll
    for (int mi = 0; mi < 4; mi++)
#pragma unroll
        for (int ni = 0; ni < 4; ni++)
#pragma unroll
            for (int q = 0; q < 4; q++) cx.acc[mi][ni][q] = 0.f;

    const int NC = K >> 5;

#pragma unroll
    for (int s = 0; s < 2; s++) {
        const __half* An = Ap + (s << 5);
        const __half* Bn = Bp + (size_t)(s << 5) * N;
        CP16(s2u(&As[s][ar][ac]), An);
        CP16(s2u(&As[s][ar][ac + 8]), An + 8);
        CP16(s2u(&Bs[s][brr][bcc]), Bn);
        CP16(s2u(&Bs[s][brr][bcc + 8]), Bn + 8);
        CP_COMMIT();
    }

    for (int kc = 0; kc < NC; kc++) {
        CP_WAIT1();
        __syncthreads();

        const int cur = kc % 3;
#pragma unroll
        for (int ks = 0; ks < 2; ks++) {
            uint32_t af[4][4];
#pragma unroll
            for (int mi = 0; mi < 4; mi++)
                LDSM4(af[mi][0], af[mi][1], af[mi][2], af[mi][3],
                      s2u(&As[cur][a_r + mi * 16][ks * 16 + a_c]));
            uint32_t bf[4][2];
#pragma unroll
            for (int nq = 0; nq < 2; nq++)
                LDSM4T(bf[2 * nq][0], bf[2 * nq][1],
                       bf[2 * nq + 1][0], bf[2 * nq + 1][1],
                       s2u(&Bs[cur][ks * 16 + b_k][cx.wn + nq * 16 + b_n]));
#pragma unroll
            for (int mi = 0; mi < 4; mi++)
#pragma unroll
                for (int ni = 0; ni < 4; ni++)
                    MMA_F16(cx.acc[mi][ni], af[mi][0], af[mi][1], af[mi][2], af[mi][3],
                            bf[ni][0], bf[ni][1]);
        }

        const int nxt = kc + 2;
        if (nxt < NC) {
            const int sb = nxt % 3;
            const __half* An = Ap + (nxt << 5);
            const __half* Bn = Bp + (size_t)(nxt << 5) * N;
            CP16(s2u(&As[sb][ar][ac]), An);
            CP16(s2u(&As[sb][ar][ac + 8]), An + 8);
            CP16(s2u(&Bs[sb][brr][bcc]), Bn);
            CP16(s2u(&Bs[sb][brr][bcc + 8]), Bn + 8);
        }
        CP_COMMIT();
    }
}

// ===========================================================================
// Variant B (R11): CTA 128x256, 256 thr, 8 warps (2x4) of 64x64, 1 CTA/SM.
// Dynamic smem: As[3][128][40] + Bs[3][32][264] = 81408 B.
// ===========================================================================
#define AS_STAGE_B (128 * 40)
#define BS_STAGE_B (32 * 264)
#define GEMM_SMEM_B ((3 * AS_STAGE_B + 3 * BS_STAGE_B) * 2)  // 81408 B

struct CtxB {
    int wm, wn, g, tg;
    float acc[4][8][4];
};

__device__ __forceinline__ void mainloop_b(
    const __half* __restrict__ A, const __half* __restrict__ B,
    int N, int K, int brow, int bcol, __half* gsm, CtxB& cx)
{
    __half (*As)[128][40] = (__half(*)[128][40])gsm;
    __half (*Bs)[32][264] = (__half(*)[32][264])(gsm + 3 * AS_STAGE_B);

    const int tid = threadIdx.x;
    const int wid = tid >> 5;
    const int lid = tid & 31;
    cx.g  = lid >> 2;
    cx.tg = lid & 3;
    cx.wm = (wid & 1) * 64;
    cx.wn = (wid >> 1) * 64;

    const int ar = tid >> 1, ac = (tid & 1) * 16;
    const int brr = tid >> 3, bcc = (tid & 7) * 32;
    const __half* Ap = A + (size_t)(brow + ar) * K + ac;
    const __half* Bp = B + (size_t)brr * N + bcol + bcc;

    const int a_r = cx.wm + (lid & 15);
    const int a_c = 8 * (lid >> 4);
    const int b_k = (lid & 7) + 8 * ((lid >> 3) & 1);
    const int b_n = 8 * (lid >> 4);

#pragma unroll
    for (int mi = 0; mi < 4; mi++)
#pragma unroll
        for (int ni = 0; ni < 8; ni++)
#pragma unroll
            for (int q = 0; q < 4; q++) cx.acc[mi][ni][q] = 0.f;

    const int NC = K >> 5;

#pragma unroll
    for (int s = 0; s < 2; s++) {
        const __half* An = Ap + (s << 5);
        const __half* Bn = Bp + (size_t)(s << 5) * N;
        CP16(s2u(&As[s][ar][ac]), An);
        CP16(s2u(&As[s][ar][ac + 8]), An + 8);
#pragma unroll
        for (int j = 0; j < 4; j++)
            CP16(s2u(&Bs[s][brr][bcc + 8 * j]), Bn + 8 * j);
        CP_COMMIT();
    }

    for (int kc = 0; kc < NC; kc++) {
        CP_WAIT1();
        __syncthreads();

        const int cur = kc % 3;
#pragma unroll
        for (int ks = 0; ks < 2; ks++) {
            uint32_t af[4][4];
#pragma unroll
            for (int mi = 0; mi < 4; mi++)
                LDSM4(af[mi][0], af[mi][1], af[mi][2], af[mi][3],
                      s2u(&As[cur][a_r + mi * 16][ks * 16 + a_c]));
            uint32_t bf[8][2];
#pragma unroll
            for (int nq = 0; nq < 4; nq++)
                LDSM4T(bf[2 * nq][0], bf[2 * nq][1],
                       bf[2 * nq + 1][0], bf[2 * nq + 1][1],
                       s2u(&Bs[cur][ks * 16 + b_k][cx.wn + nq * 16 + b_n]));
#pragma unroll
            for (int mi = 0; mi < 4; mi++)
#pragma unroll
                for (int ni = 0; ni < 8; ni++)
                    MMA_F16(cx.acc[mi][ni], af[mi][0], af[mi][1], af[mi][2], af[mi][3],
                            bf[ni][0], bf[ni][1]);
        }

        const int nxt = kc + 2;
        if (nxt < NC) {
            const int sb = nxt % 3;
            const __half* An = Ap + (nxt << 5);
            const __half* Bn = Bp + (size_t)(nxt << 5) * N;
            CP16(s2u(&As[sb][ar][ac]), An);
            CP16(s2u(&As[sb][ar][ac + 8]), An + 8);
#pragma unroll
            for (int j = 0; j < 4; j++)
                CP16(s2u(&Bs[sb][brr][bcc + 8 * j]), Bn + 8 * j);
        }
        CP_COMMIT();
    }
}

// ---------------------------------------------------------------------------
// Fused QKV projection (Variant A): X @ Wcat -> Q (RoPE), K (RoPE), V.
// ---------------------------------------------------------------------------
__global__ __launch_bounds__(256, 2) void gemm_qkv(
    const __half* __restrict__ X, const __half* __restrict__ Wc,
    __half* __restrict__ Q, __half* __restrict__ K, __half* __restrict__ V,
    const float* __restrict__ cs, const float* __restrict__ sn)
{
    extern __shared__ __half gsm[];
    const int brow = blockIdx.y * 128;
    const int bcol = blockIdx.x * 128;

    CtxA cx;
    mainloop_a(X, Wc, NCAT, DIMq, brow, bcol, gsm, cx);

    __half* C;
    int coff, Nout;
    bool rope;
    if (bcol < QDIM)              { C = Q; coff = 0;            Nout = QDIM;  rope = true;  }
    else if (bcol < QDIM + KVDIM) { C = K; coff = QDIM;         Nout = KVDIM; rope = true;  }
    else                          { C = V; coff = QDIM + KVDIM; Nout = KVDIM; rope = false; }

#pragma unroll
    for (int mi = 0; mi < 4; mi++) {
#pragma unroll
        for (int ni = 0; ni < 4; ni++) {
            const int row = brow + cx.wm + mi * 16 + cx.g;
            const int col = bcol - coff + cx.wn + ni * 8 + 2 * cx.tg;
            float* a = cx.acc[mi][ni];
            if (rope) {
                const int pair = (col & 63) >> 1;
                const int sp0 = row & (Sq - 1);
                const int sp1 = (row + 8) & (Sq - 1);
                float c0 = cs[sp0 * 32 + pair], s0 = sn[sp0 * 32 + pair];
                float c1 = cs[sp1 * 32 + pair], s1 = sn[sp1 * 32 + pair];
                *(__half2*)&C[(size_t)row * Nout + col] =
                    __floats2half2_rn(a[0] * c0 - a[1] * s0, a[0] * s0 + a[1] * c0);
                *(__half2*)&C[(size_t)(row + 8) * Nout + col] =
                    __floats2half2_rn(a[2] * c1 - a[3] * s1, a[2] * s1 + a[3] * c1);
            } else {
                *(__half2*)&C[(size_t)row * Nout + col] = __floats2half2_rn(a[0], a[1]);
                *(__half2*)&C[(size_t)(row + 8) * Nout + col] = __floats2half2_rn(a[2], a[3]);
            }
        }
    }
}

// ---------------------------------------------------------------------------
// Output projection (Variant B): O @ Wo -> out (fp32). CTA 128x256.
// ---------------------------------------------------------------------------
__global__ __launch_bounds__(256, 1) void gemm_out(
    const __half* __restrict__ A, const __half* __restrict__ B,
    float* __restrict__ C, int N, int K)
{
    extern __shared__ __half gsm[];
    const int brow = blockIdx.y * 128;
    const int bcol = blockIdx.x * 256;

    CtxB cx;
    mainloop_b(A, B, N, K, brow, bcol, gsm, cx);

#pragma unroll
    for (int mi = 0; mi < 4; mi++) {
#pragma unroll
        for (int ni = 0; ni < 8; ni++) {
            const int row = brow + cx.wm + mi * 16 + cx.g;
            const int col = bcol + cx.wn + ni * 8 + 2 * cx.tg;
            *(float2*)&C[(size_t)row * N + col] =
                make_float2(cx.acc[mi][ni][0], cx.acc[mi][ni][1]);
            *(float2*)&C[(size_t)(row + 8) * N + col] =
                make_float2(cx.acc[mi][ni][2], cx.acc[mi][ni][3]);
        }
    }
}

// ---------------------------------------------------------------------------
// fp16 flash attention (causal, GQA 4:1) — exact R10 version.
// ---------------------------------------------------------------------------
#define FS 72
#define KV_STAGE (128 * FS)
#define FLASH_SMEM (3 * KV_STAGE * 2)  // 55296 B

__global__ __launch_bounds__(256, 2) void flash_h(
    const __half* __restrict__ Q, const __half* __restrict__ K,
    const __half* __restrict__ V, __half* __restrict__ O)
{
    extern __shared__ __half fsm[];

    const int bh  = blockIdx.y;
    const int b   = bh >> 5;
    const int h   = bh & 31;
    const int kvh = h >> 2;
    const int qb  = gridDim.x - 1 - blockIdx.x;
    const int q0  = qb * 128;

    const int tid = threadIdx.x;
    const int wid = tid >> 5;
    const int lid = tid & 31;
    const int g   = lid >> 2;
    const int tg  = lid & 3;
    const int wq  = wid * 16;

    const int a_r = (lid & 15);
    const int a_c = 8 * (lid >> 4);
    const int nt_r = (lid & 7) + 8 * (lid >> 4);
    const int nt_c = 8 * ((lid >> 3) & 1);
    const int tr_r = (lid & 7) + 8 * ((lid >> 3) & 1);
    const int tr_c = 8 * (lid >> 4);

    {
        __half* Qs = fsm;
        const int row = tid >> 1, c0 = (tid & 1) * 32;
        const __half* src = &Q[((size_t)(b * Sq + q0 + row)) * QDIM + h * HDq + c0];
        const __half2 hs = __floats2half2_rn(0.125f, 0.125f);
#pragma unroll
        for (int i = 0; i < 4; i++) {
            uint4 u = *(const uint4*)(src + 8 * i);
            __half2* hp = (__half2*)&u;
#pragma unroll
            for (int j = 0; j < 4; j++) hp[j] = __hmul2(hp[j], hs);
            *(uint4*)&Qs[row * FS + c0 + 8 * i] = u;
        }
    }
    __syncthreads();

    uint32_t qf[4][4];
#pragma unroll
    for (int kc = 0; kc < 4; kc++)
        LDSM4(qf[kc][0], qf[kc][1], qf[kc][2], qf[kc][3],
              s2u(&fsm[(wq + a_r) * FS + kc * 16 + a_c]));
    __syncthreads();

    float oacc[8][4];
#pragma unroll
    for (int nj = 0; nj < 8; nj++)
#pragma unroll
        for (int q = 0; q < 4; q++) oacc[nj][q] = 0.f;
    float m0 = -1e30f, m1 = -1e30f, l0 = 0.f, l1 = 0.f;

    const int ntiles = 2 * qb + 2;
    const int row0 = q0 + wq + g;
    const int row1 = row0 + 8;

    const int kvrow = tid >> 2, kvc = (tid & 3) * 16;
    const size_t kvbase = ((size_t)b * Sq + kvrow) * KVDIM + kvh * HDq + kvc;

#pragma unroll
    for (int s = 0; s < 2; s++) {
        __half* Ks = fsm + s * KV_STAGE;
        __half* Vs = Ks + 64 * FS;
        const size_t off = kvbase + (size_t)s * 64 * KVDIM;
#pragma unroll
        for (int i = 0; i < 2; i++) {
            CP16(s2u(&Ks[kvrow * FS + kvc + 8 * i]), K + off + 8 * i);
            CP16(s2u(&Vs[kvrow * FS + kvc + 8 * i]), V + off + 8 * i);
        }
        CP_COMMIT();
    }

    for (int t = 0; t < ntiles; t++) {
        CP_WAIT1();
        __syncthreads();

        const __half* Ks = fsm + (t % 3) * KV_STAGE;
        const __half* Vs = Ks + 64 * FS;
        const int tb = t * 64;

        float sacc[8][4];
#pragma unroll
        for (int ni = 0; ni < 8; ni++)
#pragma unroll
            for (int q = 0; q < 4; q++) sacc[ni][q] = 0.f;

#pragma unroll
        for (int kc = 0; kc < 4; kc++) {
#pragma unroll
            for (int ng = 0; ng < 4; ng++) {
                uint32_t kf[4];
                LDSM4(kf[0], kf[1], kf[2], kf[3],
                      s2u(&Ks[(ng * 16 + nt_r) * FS + kc * 16 + nt_c]));
                MMA_F16(sacc[2 * ng],     qf[kc][0], qf[kc][1], qf[kc][2], qf[kc][3], kf[0], kf[1]);
                MMA_F16(sacc[2 * ng + 1], qf[kc][0], qf[kc][1], qf[kc][2], qf[kc][3], kf[2], kf[3]);
            }
        }

        if (tb + 63 > q0 + wq) {
#pragma unroll
            for (int ni = 0; ni < 8; ni++) {
                int key = tb + 8 * ni + 2 * tg;
                if (key > row0)     sacc[ni][0] = -1e30f;
                if (key + 1 > row0) sacc[ni][1] = -1e30f;
                if (key > row1)     sacc[ni][2] = -1e30f;
                if (key + 1 > row1) sacc[ni][3] = -1e30f;
            }
        }

        float tmax0 = -1e30f, tmax1 = -1e30f;
#pragma unroll
        for (int ni = 0; ni < 8; ni++) {
            tmax0 = fmaxf(tmax0, fmaxf(sacc[ni][0], sacc[ni][1]));
            tmax1 = fmaxf(tmax1, fmaxf(sacc[ni][2], sacc[ni][3]));
        }
        tmax0 = fmaxf(tmax0, __shfl_xor_sync(0xffffffff, tmax0, 1));
        tmax0 = fmaxf(tmax0, __shfl_xor_sync(0xffffffff, tmax0, 2));
        tmax1 = fmaxf(tmax1, __shfl_xor_sync(0xffffffff, tmax1, 1));
        tmax1 = fmaxf(tmax1, __shfl_xor_sync(0xffffffff, tmax1, 2));

        float nm0 = fmaxf(m0, tmax0);
        float nm1 = fmaxf(m1, tmax1);
        float corr0 = __expf(m0 - nm0);
        float corr1 = __expf(m1 - nm1);

        float rs0 = 0.f, rs1 = 0.f;
#pragma unroll
        for (int ni = 0; ni < 8; ni++) {
            sacc[ni][0] = __expf(sacc[ni][0] - nm0);
            sacc[ni][1] = __expf(sacc[ni][1] - nm0);
            sacc[ni][2] = __expf(sacc[ni][2] - nm1);
            sacc[ni][3] = __expf(sacc[ni][3] - nm1);
            rs0 += sacc[ni][0] + sacc[ni][1];
            rs1 += sacc[ni][2] + sacc[ni][3];
        }
        rs0 += __shfl_xor_sync(0xffffffff, rs0, 1);
        rs0 += __shfl_xor_sync(0xffffffff, rs0, 2);
        rs1 += __shfl_xor_sync(0xffffffff, rs1, 1);
        rs1 += __shfl_xor_sync(0xffffffff, rs1, 2);

        l0 = l0 * corr0 + rs0;
        l1 = l1 * corr1 + rs1;
#pragma unroll
        for (int nj = 0; nj < 8; nj++) {
            oacc[nj][0] *= corr0;
            oacc[nj][1] *= corr0;
            oacc[nj][2] *= corr1;
            oacc[nj][3] *= corr1;
        }
        m0 = nm0;
        m1 = nm1;

#pragma unroll
        for (int kc = 0; kc < 4; kc++) {
            uint32_t a0 = f2h2u(sacc[2 * kc][0], sacc[2 * kc][1]);
            uint32_t a1 = f2h2u(sacc[2 * kc][2], sacc[2 * kc][3]);
            uint32_t a2 = f2h2u(sacc[2 * kc + 1][0], sacc[2 * kc + 1][1]);
            uint32_t a3 = f2h2u(sacc[2 * kc + 1][2], sacc[2 * kc + 1][3]);
#pragma unroll
            for (int ng = 0; ng < 4; ng++) {
                uint32_t vf[4];
                LDSM4T(vf[0], vf[1], vf[2], vf[3],
                       s2u(&Vs[(kc * 16 + tr_r) * FS + ng * 16 + tr_c]));
                MMA_F16(oacc[2 * ng],     a0, a1, a2, a3, vf[0], vf[1]);
                MMA_F16(oacc[2 * ng + 1], a0, a1, a2, a3, vf[2], vf[3]);
            }
        }

        const int nxt = t + 2;
        if (nxt < ntiles) {
            __half* Kn = fsm + (nxt % 3) * KV_STAGE;
            __half* Vn = Kn + 64 * FS;
            const size_t off = kvbase + (size_t)nxt * 64 * KVDIM;
#pragma unroll
            for (int i = 0; i < 2; i++) {
                CP16(s2u(&Kn[kvrow * FS + kvc + 8 * i]), K + off + 8 * i);
                CP16(s2u(&Vn[kvrow * FS + kvc + 8 * i]), V + off + 8 * i);
            }
        }
        CP_COMMIT();
    }

    float inv0 = 1.f / l0;
    float inv1 = 1.f / l1;
    const size_t tok0 = (size_t)b * Sq + row0;
#pragma unroll
    for (int nj = 0; nj < 8; nj++) {
        const int col = h * HDq + 8 * nj + 2 * tg;
        *(__half2*)&O[tok0 * QDIM + col] =
            __floats2half2_rn(oacc[nj][0] * inv0, oacc[nj][1] * inv0);
        *(__half2*)&O[(tok0 + 8) * QDIM + col] =
            __floats2half2_rn(oacc[nj][2] * inv1, oacc[nj][3] * inv1);
    }
}

// ---------------------------------------------------------------------------
// Launch
// ---------------------------------------------------------------------------
extern "C" void kernel_launch(void* const* d_in, const int* in_sizes, int n_in,
                              void* d_out, int out_size)
{
    const float* x   = (const float*)d_in[0];
    const float* cs  = (const float*)d_in[1];
    const float* sn  = (const float*)d_in[2];
    const float* Wq  = (const float*)d_in[3];
    const float* Wk  = (const float*)d_in[4];
    const float* Wv  = (const float*)d_in[5];
    const float* Wo  = (const float*)d_in[6];
    float* out = (float*)d_out;

    __half *Xh, *Wcat, *Woh, *Q, *K, *V, *O;
    cudaGetSymbolAddress((void**)&Xh, g_Xh);
    cudaGetSymbolAddress((void**)&Wcat, g_Wcat);
    cudaGetSymbolAddress((void**)&Woh, g_Woh);
    cudaGetSymbolAddress((void**)&Q, g_Q);
    cudaGetSymbolAddress((void**)&K, g_K);
    cudaGetSymbolAddress((void**)&V, g_V);
    cudaGetSymbolAddress((void**)&O, g_O);

    cudaFuncSetAttribute(gemm_qkv, cudaFuncAttributeMaxDynamicSharedMemorySize, GEMM_SMEM_A);
    cudaFuncSetAttribute(gemm_out, cudaFuncAttributeMaxDynamicSharedMemorySize, GEMM_SMEM_B);
    cudaFuncSetAttribute(flash_h, cudaFuncAttributeMaxDynamicSharedMemorySize, FLASH_SMEM);

    // One fused staging kernel
    stage_all<<<9216, 256>>>(x, Wq, Wk, Wv, Wo, Xh, Wcat, Woh);

    // Fused QKV projection (+RoPE on Q,K): Variant A (128x128, 2 CTA/SM)
    gemm_qkv<<<dim3(NCAT / 128, NTOK / 128), 256, GEMM_SMEM_A>>>(Xh, Wcat, Q, K, V, cs, sn);

    // fp16 flash attention
    flash_h<<<dim3(Sq / 128, Bq * NHq), 256, FLASH_SMEM>>>(Q, K, V, O);

    // Output projection (fp32 out): Variant B (128x256, 1 CTA/SM)
    gemm_out<<<dim3(DIMq / 256, NTOK / 128), 256, GEMM_SMEM_B>>>(O, Woh, out, DIMq, QDIM);
}